// round 1
// baseline (speedup 1.0000x reference)
#include <cuda_runtime.h>
#include <cstdint>

#define EPS 1e-5f

// ---------------- scratch (static __device__ — no allocation) ----------------
__device__ float g_k1[16 * 16 * 4 * 25];
__device__ float g_k2[16 * 16 * 16 * 25];
__device__ float g_k3[16 * 32 * 16 * 25];
__device__ float g_k4[16 * 32 * 32 * 25];
__device__ float g_k5[16 * 64 * 32 * 25];
__device__ float g_k6[16 * 64 * 64 * 25];
__device__ float g_k7[16 * 4 * 64];

__device__ float g_t1[16 * 16 * 256 * 256];
__device__ float g_t2[16 * 16 * 256 * 256];
__device__ float g_t3[16 * 16 * 128 * 128];
__device__ float g_t4[16 * 32 * 128 * 128];
__device__ float g_t5[16 * 32 * 128 * 128];
__device__ float g_t6[16 * 64 * 128 * 128];
__device__ float g_t7[16 * 64 * 128 * 128];
__device__ float g_t8[16 * 4 * 128 * 128];

// per-layer BN affine: [layer][b*C + c][2] ; max C = 64
__device__ float g_aff[7 * 16 * 64 * 2];

// ---------------- per-batch weight generation ----------------
__global__ void genw_kernel(const float* __restrict__ w, const float* __restrict__ bias,
                            const int* __restrict__ action, float* __restrict__ out, int od) {
    int i = blockIdx.x * blockDim.x + threadIdx.x;
    int total = od * 16;
    if (i >= total) return;
    int b = i / od, o = i - b * od;
    out[i] = w[o * 6 + action[b]] + bias[o];
}

// ---------------- per-(b,c) BN stats -> affine (scale,bias) ----------------
template <int N>
__global__ void stats_kernel(const float* __restrict__ in, const float* __restrict__ s,
                             const float* __restrict__ bb, float* __restrict__ aff, int C) {
    int bc = blockIdx.x;  // b*C + c
    const float* p = in + (size_t)bc * N;
    float sum = 0.f, sq = 0.f;
    for (int i = threadIdx.x; i < N; i += 256) {
        float v = p[i];
        sum += v;
        sq += v * v;
    }
    __shared__ float ssum[256], ssq[256];
    ssum[threadIdx.x] = sum;
    ssq[threadIdx.x] = sq;
    __syncthreads();
    for (int st = 128; st > 0; st >>= 1) {
        if (threadIdx.x < st) {
            ssum[threadIdx.x] += ssum[threadIdx.x + st];
            ssq[threadIdx.x] += ssq[threadIdx.x + st];
        }
        __syncthreads();
    }
    if (threadIdx.x == 0) {
        int c = bc % C;
        float mean = ssum[0] / (float)N;
        float var = ssq[0] / (float)N - mean * mean;
        float sc = rsqrtf(var + EPS) * s[c];
        aff[2 * bc] = sc;
        aff[2 * bc + 1] = bb[c] - mean * sc;
    }
}

// ---------------- direct 5x5 conv (dil 1 or 2), input BN-affine fused ----------------
// Block: 32x8 threads. Tile: 32x32 output pixels. Each thread: 4 pixels x 8 out chans.
template <int CIN, int COUT, int H, int DIL, bool AFF, bool RELU>
__global__ __launch_bounds__(256) void conv5_kernel(const float* __restrict__ in,
                                                    const float* __restrict__ aff,
                                                    const float* __restrict__ wts,
                                                    float* __restrict__ out) {
    constexpr int R = 2 * DIL;
    constexpr int PS = 32 + 2 * R;
    constexpr int TPR = H / 32;

    __shared__ float patch[4][PS][PS];
    __shared__ float wsh[8][4][25];

    int tx = threadIdx.x, ty = threadIdx.y;
    int tid = ty * 32 + tx;
    int tile = blockIdx.x;
    int tix = tile % TPR, tiy = tile / TPR;
    int cog = blockIdx.y;  // output-channel group of 8
    int b = blockIdx.z;
    int x0 = tix * 32 - R, y0 = tiy * 32 - R;

    float acc[4][8];
#pragma unroll
    for (int j = 0; j < 4; j++)
#pragma unroll
        for (int co = 0; co < 8; co++) acc[j][co] = 0.f;

    const float* inb = in + (size_t)b * CIN * H * H;
    const float* affb = aff + b * CIN * 2;

    for (int cc = 0; cc < CIN; cc += 4) {
        __syncthreads();
        // load 4-channel input patch with fused BN affine (+ optional ReLU)
        for (int idx = tid; idx < 4 * PS * PS; idx += 256) {
            int c = idx / (PS * PS);
            int rem = idx - c * PS * PS;
            int py = rem / PS, px = rem - py * PS;
            int gy = y0 + py, gx = x0 + px;
            float v = 0.f;
            if (gy >= 0 && gy < H && gx >= 0 && gx < H) {
                v = inb[((size_t)(cc + c) * H + gy) * H + gx];
                if (AFF) {
                    float sc = __ldg(&affb[2 * (cc + c)]);
                    float bi = __ldg(&affb[2 * (cc + c) + 1]);
                    v = fmaf(v, sc, bi);
                    if (RELU) v = fmaxf(v, 0.f);
                }
            }
            patch[c][py][px] = v;
        }
        // load 8x4x25 weight slice
        const float* wb = wts + ((size_t)b * COUT + cog * 8) * CIN * 25 + (size_t)cc * 25;
        for (int idx = tid; idx < 800; idx += 256) {
            int co = idx / 100;
            int rem = idx - co * 100;
            int ci = rem / 25;
            int k = rem - ci * 25;
            wsh[co][ci][k] = wb[((size_t)co * CIN + ci) * 25 + k];
        }
        __syncthreads();

#pragma unroll
        for (int ci = 0; ci < 4; ci++) {
#pragma unroll
            for (int ky = 0; ky < 5; ky++) {
#pragma unroll
                for (int kx = 0; kx < 5; kx++) {
                    float wv[8];
#pragma unroll
                    for (int co = 0; co < 8; co++) wv[co] = wsh[co][ci][ky * 5 + kx];
#pragma unroll
                    for (int j = 0; j < 4; j++) {
                        float v = patch[ci][ty + 8 * j + ky * DIL][tx + kx * DIL];
#pragma unroll
                        for (int co = 0; co < 8; co++) acc[j][co] = fmaf(v, wv[co], acc[j][co]);
                    }
                }
            }
        }
    }

    int ox = tix * 32 + tx;
#pragma unroll
    for (int co = 0; co < 8; co++) {
        float* ob = out + ((size_t)b * COUT + cog * 8 + co) * H * H;
#pragma unroll
        for (int j = 0; j < 4; j++) {
            int oy = tiy * 32 + ty + 8 * j;
            ob[(size_t)oy * H + ox] = acc[j][co];
        }
    }
}

// ---------------- 2x2 avgpool fused with BN2 affine (affine commutes with mean) ----------------
__global__ void avgpool_kernel(const float* __restrict__ in, const float* __restrict__ aff,
                               float* __restrict__ out) {
    int idx = blockIdx.x * 256 + threadIdx.x;
    if (idx >= 16 * 16 * 128 * 128) return;
    int x = idx & 127;
    int y = (idx >> 7) & 127;
    int bc = idx >> 14;  // b*16 + c
    const float* p = in + ((size_t)bc * 256 + 2 * y) * 256 + 2 * x;
    float sc = aff[2 * bc], bi = aff[2 * bc + 1];
    float s = p[0] + p[1] + p[256] + p[257];
    out[idx] = fmaf(s * 0.25f, sc, bi);
}

// ---------------- 1x1 conv (64->4), BN6 affine fused on input ----------------
__global__ __launch_bounds__(256) void conv1x1_kernel(const float* __restrict__ in,
                                                      const float* __restrict__ aff,
                                                      const float* __restrict__ wts,
                                                      float* __restrict__ out) {
    int b = blockIdx.y;
    int p = blockIdx.x * 256 + threadIdx.x;  // pixel 0..16383
    __shared__ float wsh[4][64];
    __shared__ float sc[64], bi[64];
    int tid = threadIdx.x;
    wsh[tid >> 6][tid & 63] = wts[b * 256 + tid];
    if (tid < 64) {
        sc[tid] = aff[(b * 64 + tid) * 2];
        bi[tid] = aff[(b * 64 + tid) * 2 + 1];
    }
    __syncthreads();
    float acc[4] = {0.f, 0.f, 0.f, 0.f};
    const float* pin = in + (size_t)b * 64 * 16384 + p;
#pragma unroll 8
    for (int ci = 0; ci < 64; ci++) {
        float v = fmaf(pin[(size_t)ci * 16384], sc[ci], bi[ci]);
#pragma unroll
        for (int co = 0; co < 4; co++) acc[co] = fmaf(v, wsh[co][ci], acc[co]);
    }
#pragma unroll
    for (int co = 0; co < 4; co++) out[((size_t)b * 4 + co) * 16384 + p] = acc[co];
}

// ---------------- bilinear x2 (align_corners) + residual add ----------------
__global__ void up_add_kernel(const float* __restrict__ in, const float* __restrict__ x,
                              float* __restrict__ out) {
    int idx = blockIdx.x * 256 + threadIdx.x;
    if (idx >= 16 * 4 * 256 * 256) return;
    int ox = idx & 255;
    int oy = (idx >> 8) & 255;
    int bc = idx >> 16;  // b*4 + c
    const float r = (float)(127.0 / 255.0);
    float px = ox * r, py = oy * r;
    int x0 = (int)px, y0 = (int)py;
    float fx = px - x0, fy = py - y0;
    int x1 = min(x0 + 1, 127), y1 = min(y0 + 1, 127);
    const float* p = in + (size_t)bc * 16384;
    float v00 = p[y0 * 128 + x0], v01 = p[y0 * 128 + x1];
    float v10 = p[y1 * 128 + x0], v11 = p[y1 * 128 + x1];
    float v0 = v00 * (1.f - fx) + v01 * fx;
    float v1 = v10 * (1.f - fx) + v11 * fx;
    out[idx] = v0 * (1.f - fy) + v1 * fy + x[idx];
}

// ---------------- launch ----------------
extern "C" void kernel_launch(void* const* d_in, const int* in_sizes, int n_in,
                              void* d_out, int out_size) {
    const float* x = (const float*)d_in[0];
    const int* action = (const int*)d_in[1];
    const float* w[7];
    const float* wb[7];
    for (int i = 0; i < 7; i++) {
        w[i] = (const float*)d_in[2 + 2 * i];
        wb[i] = (const float*)d_in[3 + 2 * i];
    }
    const float* bns[7];
    const float* bnb[7];
    for (int i = 0; i < 7; i++) {
        bns[i] = (const float*)d_in[16 + 2 * i];
        bnb[i] = (const float*)d_in[17 + 2 * i];
    }

    float *k1, *k2, *k3, *k4, *k5, *k6, *k7;
    float *t1, *t2, *t3, *t4, *t5, *t6, *t7, *t8, *aff;
    cudaGetSymbolAddress((void**)&k1, g_k1);
    cudaGetSymbolAddress((void**)&k2, g_k2);
    cudaGetSymbolAddress((void**)&k3, g_k3);
    cudaGetSymbolAddress((void**)&k4, g_k4);
    cudaGetSymbolAddress((void**)&k5, g_k5);
    cudaGetSymbolAddress((void**)&k6, g_k6);
    cudaGetSymbolAddress((void**)&k7, g_k7);
    cudaGetSymbolAddress((void**)&t1, g_t1);
    cudaGetSymbolAddress((void**)&t2, g_t2);
    cudaGetSymbolAddress((void**)&t3, g_t3);
    cudaGetSymbolAddress((void**)&t4, g_t4);
    cudaGetSymbolAddress((void**)&t5, g_t5);
    cudaGetSymbolAddress((void**)&t6, g_t6);
    cudaGetSymbolAddress((void**)&t7, g_t7);
    cudaGetSymbolAddress((void**)&t8, g_t8);
    cudaGetSymbolAddress((void**)&aff, g_aff);

    const int AOFF = 16 * 64 * 2;

    // generate per-batch kernels
    const int ods[7] = {1600, 6400, 12800, 25600, 51200, 102400, 256};
    float* ks[7] = {k1, k2, k3, k4, k5, k6, k7};
    for (int i = 0; i < 7; i++) {
        int total = ods[i] * 16;
        genw_kernel<<<(total + 255) / 256, 256>>>(w[i], wb[i], action, ks[i], ods[i]);
    }

    dim3 tb(32, 8);

    // bn0 stats on x
    stats_kernel<65536><<<16 * 4, 256>>>(x, bns[0], bnb[0], aff + 0 * AOFF, 4);
    // conv1: bn0(x) -> t1 (raw)
    conv5_kernel<4, 16, 256, 2, true, false><<<dim3(64, 2, 16), tb>>>(x, aff + 0 * AOFF, k1, t1);
    // bn1 stats
    stats_kernel<65536><<<16 * 16, 256>>>(t1, bns[1], bnb[1], aff + 1 * AOFF, 16);
    // conv2: relu(bn1(t1)) -> t2 (raw)
    conv5_kernel<16, 16, 256, 1, true, true><<<dim3(64, 2, 16), tb>>>(t1, aff + 1 * AOFF, k2, t2);
    // bn2 stats
    stats_kernel<65536><<<16 * 16, 256>>>(t2, bns[2], bnb[2], aff + 2 * AOFF, 16);
    // avgpool(bn2(t2)) -> t3 (normalized)
    avgpool_kernel<<<(16 * 16 * 128 * 128 + 255) / 256, 256>>>(t2, aff + 2 * AOFF, t3);
    // conv3: t3 -> t4 (raw)
    conv5_kernel<16, 32, 128, 2, false, false><<<dim3(16, 4, 16), tb>>>(t3, aff, k3, t4);
    // bn3 stats
    stats_kernel<16384><<<16 * 32, 256>>>(t4, bns[3], bnb[3], aff + 3 * AOFF, 32);
    // conv4: relu(bn3(t4)) -> t5
    conv5_kernel<32, 32, 128, 1, true, true><<<dim3(16, 4, 16), tb>>>(t4, aff + 3 * AOFF, k4, t5);
    // bn4 stats
    stats_kernel<16384><<<16 * 32, 256>>>(t5, bns[4], bnb[4], aff + 4 * AOFF, 32);
    // conv5: bn4(t5) (no relu) -> t6
    conv5_kernel<32, 64, 128, 2, true, false><<<dim3(16, 8, 16), tb>>>(t5, aff + 4 * AOFF, k5, t6);
    // bn5 stats
    stats_kernel<16384><<<16 * 64, 256>>>(t6, bns[5], bnb[5], aff + 5 * AOFF, 64);
    // conv6: relu(bn5(t6)) -> t7
    conv5_kernel<64, 64, 128, 1, true, true><<<dim3(16, 8, 16), tb>>>(t6, aff + 5 * AOFF, k6, t7);
    // bn6 stats
    stats_kernel<16384><<<16 * 64, 256>>>(t7, bns[6], bnb[6], aff + 6 * AOFF, 64);
    // conv7 1x1: bn6(t7) -> t8
    conv1x1_kernel<<<dim3(64, 16), 256>>>(t7, aff + 6 * AOFF, k7, t8);
    // upsample + residual
    up_add_kernel<<<(16 * 4 * 256 * 256 + 255) / 256, 256>>>(t8, x, (float*)d_out);
}

// round 3
// speedup vs baseline: 1.8980x; 1.8980x over previous
#include <cuda_runtime.h>
#include <cstdint>

#define EPS 1e-5f

// ---------------- scratch (static __device__ — no allocation) ----------------
__device__ float g_k1[16 * 16 * 4 * 25];
__device__ float g_k2[16 * 16 * 16 * 25];
__device__ float g_k3[16 * 32 * 16 * 25];
__device__ float g_k4[16 * 32 * 32 * 25];
__device__ float g_k5[16 * 64 * 32 * 25];
__device__ float g_k6[16 * 64 * 64 * 25];
__device__ float g_k7[16 * 4 * 64];

__device__ float g_t1[16 * 16 * 256 * 256];
__device__ float g_t2[16 * 16 * 256 * 256];
__device__ float g_t3[16 * 16 * 128 * 128];
__device__ float g_t4[16 * 32 * 128 * 128];
__device__ float g_t5[16 * 32 * 128 * 128];
__device__ float g_t6[16 * 64 * 128 * 128];
__device__ float g_t7[16 * 64 * 128 * 128];
__device__ float g_t8[16 * 4 * 128 * 128];

// per-layer BN affine: [layer][b*C + c][2] ; max C = 64
__device__ float g_aff[7 * 16 * 64 * 2];

__device__ __forceinline__ float tf32r(float x) {
    unsigned u;
    asm("cvt.rna.tf32.f32 %0, %1;" : "=r"(u) : "f"(x));
    return __uint_as_float(u);
}

__device__ __forceinline__ void mma_tf32(float c[4], uint32_t a0, uint32_t a1, uint32_t a2,
                                         uint32_t a3, uint32_t b0, uint32_t b1) {
    asm volatile(
        "mma.sync.aligned.m16n8k8.row.col.f32.tf32.tf32.f32 "
        "{%0,%1,%2,%3},{%4,%5,%6,%7},{%8,%9},{%0,%1,%2,%3};"
        : "+f"(c[0]), "+f"(c[1]), "+f"(c[2]), "+f"(c[3])
        : "r"(a0), "r"(a1), "r"(a2), "r"(a3), "r"(b0), "r"(b1));
}

// ---------------- per-batch weight generation ----------------
// plain layout (for 1x1 conv)
__global__ void genw_kernel(const float* __restrict__ w, const float* __restrict__ bias,
                            const int* __restrict__ action, float* __restrict__ out, int od) {
    int i = blockIdx.x * blockDim.x + threadIdx.x;
    int total = od * 16;
    if (i >= total) return;
    int b = i / od, o = i - b * od;
    out[i] = w[o * 6 + action[b]] + bias[o];
}

// transposed + tf32-rounded layout for mma convs: [b][ci][tap][cout]
__global__ void genw_t_kernel(const float* __restrict__ w, const float* __restrict__ bias,
                              const int* __restrict__ action, float* __restrict__ out, int CINx,
                              int COUTx) {
    int i = blockIdx.x * blockDim.x + threadIdx.x;
    int od = COUTx * CINx * 25;
    int total = od * 16;
    if (i >= total) return;
    int b = i / od, o = i - b * od;
    int cout = o / (CINx * 25);
    int rem = o - cout * CINx * 25;
    int ci = rem / 25;
    int tap = rem - ci * 25;
    float v = w[o * 6 + action[b]] + bias[o];
    out[((size_t)(b * CINx + ci) * 25 + tap) * COUTx + cout] = tf32r(v);
}

// ---------------- per-(b,c) BN stats -> affine (scale,bias) ----------------
template <int N>
__global__ void stats_kernel(const float* __restrict__ in, const float* __restrict__ s,
                             const float* __restrict__ bb, float* __restrict__ aff, int C) {
    int bc = blockIdx.x;  // b*C + c
    const float* p = in + (size_t)bc * N;
    float sum = 0.f, sq = 0.f;
    for (int i = threadIdx.x; i < N; i += 256) {
        float v = p[i];
        sum += v;
        sq += v * v;
    }
    __shared__ float ssum[256], ssq[256];
    ssum[threadIdx.x] = sum;
    ssq[threadIdx.x] = sq;
    __syncthreads();
    for (int st = 128; st > 0; st >>= 1) {
        if (threadIdx.x < st) {
            ssum[threadIdx.x] += ssum[threadIdx.x + st];
            ssq[threadIdx.x] += ssq[threadIdx.x + st];
        }
        __syncthreads();
    }
    if (threadIdx.x == 0) {
        int c = bc % C;
        float mean = ssum[0] / (float)N;
        float var = ssq[0] / (float)N - mean * mean;
        float sc = rsqrtf(var + EPS) * s[c];
        aff[2 * bc] = sc;
        aff[2 * bc + 1] = bb[c] - mean * sc;
    }
}

// ---------------- tensor-core 5x5 conv (per-tap implicit GEMM, tf32 mma) -------------
// Block: 256 threads (8 warps). Output tile: 32x8 pixels (M=256) x COUT.
// Per warp: Mw = 64 px (COUT>=32) or 32 px (COUT=16), Nw = COUT/NSPLIT.
// A fragments read directly from padded patch smem; K = 8 input channels per mma.
template <int CIN, int COUT, int H, int DIL, bool AFF, bool RELU>
__global__ __launch_bounds__(256) void conv5_mma_kernel(const float* __restrict__ in,
                                                        const float* __restrict__ aff,
                                                        const float* __restrict__ wts,
                                                        float* __restrict__ out) {
    constexpr int R = 2 * DIL;
    constexpr int PX = 32 + 2 * R;
    constexpr int PY = 8 + 2 * R;
    constexpr int PLANE0 = PY * PX;
    constexpr int PLANE = PLANE0 + ((8 - (PLANE0 % 32)) + 32) % 32;  // ≡8 (mod 32)
    constexpr int NSPLIT = (COUT >= 32) ? 2 : 1;
    constexpr int NW = COUT / NSPLIT;
    constexpr int NT = NW / 8;
    constexpr int RPW = NSPLIT;   // pixel rows per warp
    constexpr int MT = 2 * RPW;   // m16 tiles per warp
    constexpr int WS = COUT + 8;  // wtile inner stride (bank-safe)
    constexpr int CINC = (CIN + 7) / 8;

    __shared__ float patch[8 * PLANE];
    __shared__ float wtile[5 * 8 * WS];

    int tid = threadIdx.x;
    int wid = tid >> 5, lane = tid & 31;
    int tg = lane & 3, gid = lane >> 2;
    int nw = (NSPLIT == 2) ? (wid & 1) : 0;
    int mw = (NSPLIT == 2) ? (wid >> 1) : wid;

    int bx0 = blockIdx.x * 32, by0 = blockIdx.y * 8;
    int b = blockIdx.z;

    const float* gw = wts + (size_t)b * CIN * 25 * COUT;
    const float* affb = aff + (b * CIN) * 2;
    const float* inb = in + (size_t)b * CIN * H * H;

    float acc[MT][NT][4];
#pragma unroll
    for (int mt = 0; mt < MT; mt++)
#pragma unroll
        for (int nt = 0; nt < NT; nt++)
#pragma unroll
            for (int k = 0; k < 4; k++) acc[mt][nt][k] = 0.f;

    int baseA[MT];
#pragma unroll
    for (int mt = 0; mt < MT; mt++) {
        int py_m = mw * RPW + (mt >> 1);
        int px0 = (mt & 1) * 16;
        baseA[mt] = tg * PLANE + py_m * PX + px0 + gid;
    }
    int baseB = tg * WS + nw * NW + gid;

    for (int ci0 = 0; ci0 < CIN; ci0 += 8) {
        __syncthreads();
        // load 8-channel patch, fused BN affine (+relu), tf32-round
        for (int idx = tid; idx < 8 * PLANE0; idx += 256) {
            int ci = idx / PLANE0;
            int rem = idx - ci * PLANE0;
            int py = rem / PX, px = rem - py * PX;
            int gy = by0 - R + py, gx = bx0 - R + px;
            float v = 0.f;
            int cg = ci0 + ci;
            if (cg < CIN && (unsigned)gy < (unsigned)H && (unsigned)gx < (unsigned)H) {
                v = inb[(size_t)cg * H * H + gy * H + gx];
                if (AFF) {
                    v = fmaf(v, __ldg(&affb[2 * cg]), __ldg(&affb[2 * cg + 1]));
                    if (RELU) v = fmaxf(v, 0.f);
                }
            }
            patch[ci * PLANE + py * PX + px] = tf32r(v);
        }

        for (int ky = 0; ky < 5; ky++) {
            __syncthreads();
            // stage weights for this (ci8, ky): [kx(5)][ci(8)][cout]
            for (int idx = tid; idx < 5 * 8 * COUT; idx += 256) {
                int kx = idx / (8 * COUT);
                int rem = idx - kx * 8 * COUT;
                int ci = rem / COUT;
                int n = rem - ci * COUT;
                float v = 0.f;
                if (ci0 + ci < CIN)
                    v = gw[((size_t)(ci0 + ci) * 25 + ky * 5 + kx) * COUT + n];
                wtile[(kx * 8 + ci) * WS + n] = v;
            }
            __syncthreads();

#pragma unroll
            for (int kx = 0; kx < 5; kx++) {
                uint32_t Bf[NT][2];
#pragma unroll
                for (int nt = 0; nt < NT; nt++) {
                    int ba = baseB + kx * 8 * WS + nt * 8;
                    Bf[nt][0] = __float_as_uint(wtile[ba]);
                    Bf[nt][1] = __float_as_uint(wtile[ba + 4 * WS]);
                }
#pragma unroll
                for (int mt = 0; mt < MT; mt++) {
                    int ao = baseA[mt] + ky * DIL * PX + kx * DIL;
                    uint32_t A0 = __float_as_uint(patch[ao]);
                    uint32_t A1 = __float_as_uint(patch[ao + 8]);
                    uint32_t A2 = __float_as_uint(patch[ao + 4 * PLANE]);
                    uint32_t A3 = __float_as_uint(patch[ao + 4 * PLANE + 8]);
#pragma unroll
                    for (int nt = 0; nt < NT; nt++)
                        mma_tf32(acc[mt][nt], A0, A1, A2, A3, Bf[nt][0], Bf[nt][1]);
                }
            }
        }
    }

    // store
#pragma unroll
    for (int mt = 0; mt < MT; mt++) {
        int py_m = mw * RPW + (mt >> 1);
        int px0 = (mt & 1) * 16;
        int gy = by0 + py_m;
        int gx = bx0 + px0 + gid;
#pragma unroll
        for (int nt = 0; nt < NT; nt++) {
            int cout = nw * NW + nt * 8 + 2 * tg;
            float* o0 = out + ((size_t)(b * COUT + cout) * H + gy) * H;
            o0[gx] = acc[mt][nt][0];
            o0[H * (size_t)H + gx] = acc[mt][nt][1];
            o0[gx + 8] = acc[mt][nt][2];
            o0[H * (size_t)H + gx + 8] = acc[mt][nt][3];
        }
    }
}

// ---------------- 2x2 avgpool fused with BN2 affine ----------------
__global__ void avgpool_kernel(const float* __restrict__ in, const float* __restrict__ aff,
                               float* __restrict__ out) {
    int idx = blockIdx.x * 256 + threadIdx.x;
    if (idx >= 16 * 16 * 128 * 128) return;
    int x = idx & 127;
    int y = (idx >> 7) & 127;
    int bc = idx >> 14;  // b*16 + c
    const float* p = in + ((size_t)bc * 256 + 2 * y) * 256 + 2 * x;
    float sc = aff[2 * bc], bi = aff[2 * bc + 1];
    float s = p[0] + p[1] + p[256] + p[257];
    out[idx] = fmaf(s * 0.25f, sc, bi);
}

// ---------------- 1x1 conv (64->4), BN6 affine fused on input ----------------
__global__ __launch_bounds__(256) void conv1x1_kernel(const float* __restrict__ in,
                                                      const float* __restrict__ aff,
                                                      const float* __restrict__ wts,
                                                      float* __restrict__ out) {
    int b = blockIdx.y;
    int p = blockIdx.x * 256 + threadIdx.x;  // pixel 0..16383
    __shared__ float wsh[4][64];
    __shared__ float sc[64], bi[64];
    int tid = threadIdx.x;
    wsh[tid >> 6][tid & 63] = wts[b * 256 + tid];
    if (tid < 64) {
        sc[tid] = aff[(b * 64 + tid) * 2];
        bi[tid] = aff[(b * 64 + tid) * 2 + 1];
    }
    __syncthreads();
    float acc[4] = {0.f, 0.f, 0.f, 0.f};
    const float* pin = in + (size_t)b * 64 * 16384 + p;
#pragma unroll 8
    for (int ci = 0; ci < 64; ci++) {
        float v = fmaf(pin[(size_t)ci * 16384], sc[ci], bi[ci]);
#pragma unroll
        for (int co = 0; co < 4; co++) acc[co] = fmaf(v, wsh[co][ci], acc[co]);
    }
#pragma unroll
    for (int co = 0; co < 4; co++) out[((size_t)b * 4 + co) * 16384 + p] = acc[co];
}

// ---------------- bilinear x2 (align_corners) + residual add ----------------
__global__ void up_add_kernel(const float* __restrict__ in, const float* __restrict__ x,
                              float* __restrict__ out) {
    int idx = blockIdx.x * 256 + threadIdx.x;
    if (idx >= 16 * 4 * 256 * 256) return;
    int ox = idx & 255;
    int oy = (idx >> 8) & 255;
    int bc = idx >> 16;  // b*4 + c
    const float r = (float)(127.0 / 255.0);
    float px = ox * r, py = oy * r;
    int x0 = (int)px, y0 = (int)py;
    float fx = px - x0, fy = py - y0;
    int x1 = min(x0 + 1, 127), y1 = min(y0 + 1, 127);
    const float* p = in + (size_t)bc * 16384;
    float v00 = p[y0 * 128 + x0], v01 = p[y0 * 128 + x1];
    float v10 = p[y1 * 128 + x0], v11 = p[y1 * 128 + x1];
    float v0 = v00 * (1.f - fx) + v01 * fx;
    float v1 = v10 * (1.f - fx) + v11 * fx;
    out[idx] = v0 * (1.f - fy) + v1 * fy + x[idx];
}

// ---------------- launch ----------------
extern "C" void kernel_launch(void* const* d_in, const int* in_sizes, int n_in,
                              void* d_out, int out_size) {
    const float* x = (const float*)d_in[0];
    const int* action = (const int*)d_in[1];
    const float* w[7];
    const float* wb[7];
    for (int i = 0; i < 7; i++) {
        w[i] = (const float*)d_in[2 + 2 * i];
        wb[i] = (const float*)d_in[3 + 2 * i];
    }
    const float* bns[7];
    const float* bnb[7];
    for (int i = 0; i < 7; i++) {
        bns[i] = (const float*)d_in[16 + 2 * i];
        bnb[i] = (const float*)d_in[17 + 2 * i];
    }

    float *k1, *k2, *k3, *k4, *k5, *k6, *k7;
    float *t1, *t2, *t3, *t4, *t5, *t6, *t7, *t8, *aff;
    cudaGetSymbolAddress((void**)&k1, g_k1);
    cudaGetSymbolAddress((void**)&k2, g_k2);
    cudaGetSymbolAddress((void**)&k3, g_k3);
    cudaGetSymbolAddress((void**)&k4, g_k4);
    cudaGetSymbolAddress((void**)&k5, g_k5);
    cudaGetSymbolAddress((void**)&k6, g_k6);
    cudaGetSymbolAddress((void**)&k7, g_k7);
    cudaGetSymbolAddress((void**)&t1, g_t1);
    cudaGetSymbolAddress((void**)&t2, g_t2);
    cudaGetSymbolAddress((void**)&t3, g_t3);
    cudaGetSymbolAddress((void**)&t4, g_t4);
    cudaGetSymbolAddress((void**)&t5, g_t5);
    cudaGetSymbolAddress((void**)&t6, g_t6);
    cudaGetSymbolAddress((void**)&t7, g_t7);
    cudaGetSymbolAddress((void**)&t8, g_t8);
    cudaGetSymbolAddress((void**)&aff, g_aff);

    const int AOFF = 16 * 64 * 2;

    // generate per-batch conv kernels (transposed + tf32 rounded)
    const int cins[6] = {4, 16, 16, 32, 32, 64};
    const int couts[6] = {16, 16, 32, 32, 64, 64};
    float* ks[6] = {k1, k2, k3, k4, k5, k6};
    for (int i = 0; i < 6; i++) {
        int total = couts[i] * cins[i] * 25 * 16;
        genw_t_kernel<<<(total + 255) / 256, 256>>>(w[i], wb[i], action, ks[i], cins[i], couts[i]);
    }
    genw_kernel<<<(256 * 16 + 255) / 256, 256>>>(w[6], wb[6], action, k7, 256);

    // bn0 stats on x
    stats_kernel<65536><<<16 * 4, 256>>>(x, bns[0], bnb[0], aff + 0 * AOFF, 4);
    // conv1: bn0(x) -> t1
    conv5_mma_kernel<4, 16, 256, 2, true, false>
        <<<dim3(8, 32, 16), 256>>>(x, aff + 0 * AOFF, k1, t1);
    // bn1 stats
    stats_kernel<65536><<<16 * 16, 256>>>(t1, bns[1], bnb[1], aff + 1 * AOFF, 16);
    // conv2: relu(bn1(t1)) -> t2
    conv5_mma_kernel<16, 16, 256, 1, true, true>
        <<<dim3(8, 32, 16), 256>>>(t1, aff + 1 * AOFF, k2, t2);
    // bn2 stats
    stats_kernel<65536><<<16 * 16, 256>>>(t2, bns[2], bnb[2], aff + 2 * AOFF, 16);
    // avgpool(bn2(t2)) -> t3 (normalized)
    avgpool_kernel<<<(16 * 16 * 128 * 128 + 255) / 256, 256>>>(t2, aff + 2 * AOFF, t3);
    // conv3: t3 -> t4
    conv5_mma_kernel<16, 32, 128, 2, false, false>
        <<<dim3(4, 16, 16), 256>>>(t3, aff, k3, t4);
    // bn3 stats
    stats_kernel<16384><<<16 * 32, 256>>>(t4, bns[3], bnb[3], aff + 3 * AOFF, 32);
    // conv4: relu(bn3(t4)) -> t5
    conv5_mma_kernel<32, 32, 128, 1, true, true>
        <<<dim3(4, 16, 16), 256>>>(t4, aff + 3 * AOFF, k4, t5);
    // bn4 stats
    stats_kernel<16384><<<16 * 32, 256>>>(t5, bns[4], bnb[4], aff + 4 * AOFF, 32);
    // conv5: bn4(t5) -> t6
    conv5_mma_kernel<32, 64, 128, 2, true, false>
        <<<dim3(4, 16, 16), 256>>>(t5, aff + 4 * AOFF, k5, t6);
    // bn5 stats
    stats_kernel<16384><<<16 * 64, 256>>>(t6, bns[5], bnb[5], aff + 5 * AOFF, 64);
    // conv6: relu(bn5(t6)) -> t7
    conv5_mma_kernel<64, 64, 128, 1, true, true>
        <<<dim3(4, 16, 16), 256>>>(t6, aff + 5 * AOFF, k6, t7);
    // bn6 stats
    stats_kernel<16384><<<16 * 64, 256>>>(t7, bns[6], bnb[6], aff + 6 * AOFF, 64);
    // conv7 1x1: bn6(t7) -> t8
    conv1x1_kernel<<<dim3(64, 16), 256>>>(t7, aff + 6 * AOFF, k7, t8);
    // upsample + residual
    up_add_kernel<<<(16 * 4 * 256 * 256 + 255) / 256, 256>>>(t8, x, (float*)d_out);
}

// round 4
// speedup vs baseline: 1.9311x; 1.0174x over previous
#include <cuda_runtime.h>
#include <cuda_bf16.h>
#include <cstdint>

#define EPS 1e-5f

// ---------------- scratch (static __device__ — no allocation) ----------------
// conv weights in bf16-split u2 layout: [b][chunk(CINPAD/16)][tap(25)][kpair(8)][COUT]
__device__ uint2 g_k1[16 * 1 * 25 * 8 * 16];
__device__ uint2 g_k2[16 * 1 * 25 * 8 * 16];
__device__ uint2 g_k3[16 * 1 * 25 * 8 * 32];
__device__ uint2 g_k4[16 * 2 * 25 * 8 * 32];
__device__ uint2 g_k5[16 * 2 * 25 * 8 * 64];
__device__ uint2 g_k6[16 * 4 * 25 * 8 * 64];
__device__ float g_k7[16 * 4 * 64];

__device__ float g_t1[16 * 16 * 256 * 256];
__device__ float g_t2[16 * 16 * 256 * 256];
__device__ float g_t3[16 * 16 * 128 * 128];
__device__ float g_t4[16 * 32 * 128 * 128];
__device__ float g_t5[16 * 32 * 128 * 128];
__device__ float g_t6[16 * 64 * 128 * 128];
__device__ float g_t7[16 * 64 * 128 * 128];
__device__ float g_t8[16 * 4 * 128 * 128];

// per-layer BN affine: [layer][b*C + c][2] ; max C = 64
__device__ float g_aff[7 * 16 * 64 * 2];

// ---------------- helpers ----------------
__device__ __forceinline__ uint2 bsplit2(float v0, float v1) {
    __nv_bfloat16 h0 = __float2bfloat16(v0);
    __nv_bfloat16 h1 = __float2bfloat16(v1);
    float l0 = v0 - __bfloat162float(h0);
    float l1 = v1 - __bfloat162float(h1);
    __nv_bfloat162 hi, lo;
    hi.x = h0;
    hi.y = h1;
    lo.x = __float2bfloat16(l0);
    lo.y = __float2bfloat16(l1);
    uint2 u;
    u.x = *reinterpret_cast<uint32_t*>(&hi);
    u.y = *reinterpret_cast<uint32_t*>(&lo);
    return u;
}

__device__ __forceinline__ void mma_bf16(float c[4], uint32_t a0, uint32_t a1, uint32_t a2,
                                         uint32_t a3, uint32_t b0, uint32_t b1) {
    asm volatile(
        "mma.sync.aligned.m16n8k16.row.col.f32.bf16.bf16.f32 "
        "{%0,%1,%2,%3},{%4,%5,%6,%7},{%8,%9},{%0,%1,%2,%3};"
        : "+f"(c[0]), "+f"(c[1]), "+f"(c[2]), "+f"(c[3])
        : "r"(a0), "r"(a1), "r"(a2), "r"(a3), "r"(b0), "r"(b1));
}

// ---------------- per-batch weight generation ----------------
// plain fp32 layout (for 1x1 conv)
__global__ void genw_kernel(const float* __restrict__ w, const float* __restrict__ bias,
                            const int* __restrict__ action, float* __restrict__ out, int od) {
    int i = blockIdx.x * blockDim.x + threadIdx.x;
    int total = od * 16;
    if (i >= total) return;
    int b = i / od, o = i - b * od;
    out[i] = w[o * 6 + action[b]] + bias[o];
}

// bf16-split u2 layout for mma convs
__global__ void genw_bf16_kernel(const float* __restrict__ w, const float* __restrict__ bias,
                                 const int* __restrict__ action, uint2* __restrict__ out, int CIN,
                                 int NCH, int COUT) {
    int i = blockIdx.x * 256 + threadIdx.x;
    int total = 16 * NCH * 25 * 8 * COUT;
    if (i >= total) return;
    int co = i % COUT;
    int r = i / COUT;
    int kp = r % 8;
    r /= 8;
    int tap = r % 25;
    r /= 25;
    int chv = r % NCH;
    int b = r / NCH;
    int a = action[b];
    int ci0 = chv * 16 + kp * 2;
    float v0 = 0.f, v1 = 0.f;
    if (ci0 < CIN) {
        int o = (co * CIN + ci0) * 25 + tap;
        v0 = w[o * 6 + a] + bias[o];
    }
    if (ci0 + 1 < CIN) {
        int o = (co * CIN + ci0 + 1) * 25 + tap;
        v1 = w[o * 6 + a] + bias[o];
    }
    out[i] = bsplit2(v0, v1);
}

// ---------------- per-(b,c) BN stats -> affine (scale,bias) ----------------
template <int N>
__global__ void stats_kernel(const float* __restrict__ in, const float* __restrict__ s,
                             const float* __restrict__ bb, float* __restrict__ aff, int C) {
    int bc = blockIdx.x;  // b*C + c
    const float* p = in + (size_t)bc * N;
    float sum = 0.f, sq = 0.f;
    for (int i = threadIdx.x; i < N; i += 256) {
        float v = p[i];
        sum += v;
        sq += v * v;
    }
    __shared__ float ssum[256], ssq[256];
    ssum[threadIdx.x] = sum;
    ssq[threadIdx.x] = sq;
    __syncthreads();
    for (int st = 128; st > 0; st >>= 1) {
        if (threadIdx.x < st) {
            ssum[threadIdx.x] += ssum[threadIdx.x + st];
            ssq[threadIdx.x] += ssq[threadIdx.x + st];
        }
        __syncthreads();
    }
    if (threadIdx.x == 0) {
        int c = bc % C;
        float mean = ssum[0] / (float)N;
        float var = ssq[0] / (float)N - mean * mean;
        float sc = rsqrtf(var + EPS) * s[c];
        aff[2 * bc] = sc;
        aff[2 * bc + 1] = bb[c] - mean * sc;
    }
}

// ---------------- bf16x3 tensor-core 5x5 conv (per-tap implicit GEMM) ----------------
// 256 threads (8 warps). Output tile: 32 x TH pixels, COUT_B output channels.
// hi/lo bf16 pairs packed in uint2; 3 mmas (hh, hl, lh) per k16 per tile.
template <int CIN, int COUT, int COUT_B, int H, int DIL, int TH, bool AFF, bool RELU>
__global__ __launch_bounds__(256, 2) void conv5_bf16_kernel(const float* __restrict__ in,
                                                            const float* __restrict__ aff,
                                                            const uint2* __restrict__ wts,
                                                            float* __restrict__ out) {
    constexpr int R = 2 * DIL;
    constexpr int PX = 32 + 2 * R;
    constexpr int PY = TH + 2 * R;
    constexpr int PLANE0 = PX * PY;
    constexpr int PS = PLANE0 + ((4 - PLANE0 % 16) + 16) % 16;  // ≡4 (mod 16) u2 units
    constexpr int WS = COUT_B + 4;
    constexpr int NT = COUT_B / 8;
    constexpr int MT = (TH / 8) * 2;
    constexpr int RPW = TH / 8;
    constexpr int CGRP = COUT / COUT_B;
    constexpr int CINPAD = (CIN + 15) & ~15;
    constexpr int NCH = CINPAD / 16;

    extern __shared__ uint2 sm[];
    uint2* wtile = sm;                // [25][8][WS]
    uint2* patch = sm + 25 * 8 * WS;  // [8 pairs][PS]

    int tid = threadIdx.x, wid = tid >> 5, lane = tid & 31;
    int tg = lane & 3, gid = lane >> 2;
    int bx0 = blockIdx.x * 32;
    int ytile = blockIdx.y / CGRP;
    int cg = blockIdx.y % CGRP;
    int by0 = ytile * TH;
    int b = blockIdx.z;
    int co0 = cg * COUT_B;

    const float* inb = in + (size_t)b * CIN * H * H;
    const float* affb = aff + b * CIN * 2;
    const uint2* wb = wts + ((size_t)b * NCH * 25 * 8) * COUT + co0;

    float acc[MT][NT][4];
#pragma unroll
    for (int mt = 0; mt < MT; mt++)
#pragma unroll
        for (int nt = 0; nt < NT; nt++)
#pragma unroll
            for (int k = 0; k < 4; k++) acc[mt][nt][k] = 0.f;

    int baseA[MT];
#pragma unroll
    for (int mt = 0; mt < MT; mt++) {
        int rofs = (MT == 4) ? (mt >> 1) : 0;
        int pxo = ((MT == 4) ? (mt & 1) : mt) * 16;
        baseA[mt] = tg * PS + (wid * RPW + rofs) * PX + pxo + gid;
    }

    for (int ch = 0; ch < NCH; ch++) {
        __syncthreads();
        // ---- load 16-channel patch (8 hi/lo channel-pair planes) ----
        for (int idx = tid; idx < 8 * PLANE0; idx += 256) {
            int p = idx / PLANE0;
            int rem = idx - p * PLANE0;
            int py = rem / PX, px = rem - py * PX;
            int gy = by0 - R + py, gx = bx0 - R + px;
            int c0 = ch * 16 + 2 * p;
            float v0 = 0.f, v1 = 0.f;
            if ((unsigned)gy < (unsigned)H && (unsigned)gx < (unsigned)H) {
                if (c0 < CIN) {
                    v0 = inb[((size_t)c0 * H + gy) * H + gx];
                    if (AFF) {
                        v0 = fmaf(v0, __ldg(affb + 2 * c0), __ldg(affb + 2 * c0 + 1));
                        if (RELU) v0 = fmaxf(v0, 0.f);
                    }
                }
                if (c0 + 1 < CIN) {
                    v1 = inb[((size_t)(c0 + 1) * H + gy) * H + gx];
                    if (AFF) {
                        v1 = fmaf(v1, __ldg(affb + 2 * c0 + 2), __ldg(affb + 2 * c0 + 3));
                        if (RELU) v1 = fmaxf(v1, 0.f);
                    }
                }
            }
            patch[p * PS + py * PX + px] = bsplit2(v0, v1);
        }
        // ---- stage all 25 taps of weights for this chunk ----
        const uint2* wc = wb + (size_t)ch * 25 * 8 * COUT;
        for (int idx = tid; idx < 25 * 8 * COUT_B; idx += 256) {
            int t8 = idx / COUT_B;
            int co = idx - t8 * COUT_B;
            wtile[t8 * WS + co] = wc[(size_t)t8 * COUT + co];
        }
        __syncthreads();

#pragma unroll
        for (int ky = 0; ky < 5; ky++) {
#pragma unroll
            for (int kx = 0; kx < 5; kx++) {
                const uint2* wt = wtile + (ky * 5 + kx) * 8 * WS;
                uint2 Bf[NT][2];
#pragma unroll
                for (int nt = 0; nt < NT; nt++) {
                    Bf[nt][0] = wt[tg * WS + nt * 8 + gid];
                    Bf[nt][1] = wt[(tg + 4) * WS + nt * 8 + gid];
                }
#pragma unroll
                for (int mt = 0; mt < MT; mt++) {
                    int ao = baseA[mt] + ky * DIL * PX + kx * DIL;
                    uint2 A0 = patch[ao];
                    uint2 A1 = patch[ao + 8];
                    uint2 A2 = patch[ao + 4 * PS];
                    uint2 A3 = patch[ao + 4 * PS + 8];
#pragma unroll
                    for (int nt = 0; nt < NT; nt++) {
                        mma_bf16(acc[mt][nt], A0.x, A1.x, A2.x, A3.x, Bf[nt][0].x, Bf[nt][1].x);
                        mma_bf16(acc[mt][nt], A0.x, A1.x, A2.x, A3.x, Bf[nt][0].y, Bf[nt][1].y);
                        mma_bf16(acc[mt][nt], A0.y, A1.y, A2.y, A3.y, Bf[nt][0].x, Bf[nt][1].x);
                    }
                }
            }
        }
    }

    // ---- epilogue ----
#pragma unroll
    for (int mt = 0; mt < MT; mt++) {
        int rofs = (MT == 4) ? (mt >> 1) : 0;
        int pxo = ((MT == 4) ? (mt & 1) : mt) * 16;
        int gy = by0 + wid * RPW + rofs;
        int gx = bx0 + pxo + gid;
#pragma unroll
        for (int nt = 0; nt < NT; nt++) {
            int co = co0 + nt * 8 + 2 * tg;
            float* o = out + ((size_t)(b * COUT + co) * H + gy) * H;
            o[gx] = acc[mt][nt][0];
            o[(size_t)H * H + gx] = acc[mt][nt][1];
            o[gx + 8] = acc[mt][nt][2];
            o[(size_t)H * H + gx + 8] = acc[mt][nt][3];
        }
    }
}

// ---------------- 2x2 avgpool fused with BN2 affine ----------------
__global__ void avgpool_kernel(const float* __restrict__ in, const float* __restrict__ aff,
                               float* __restrict__ out) {
    int idx = blockIdx.x * 256 + threadIdx.x;
    if (idx >= 16 * 16 * 128 * 128) return;
    int x = idx & 127;
    int y = (idx >> 7) & 127;
    int bc = idx >> 14;  // b*16 + c
    const float* p = in + ((size_t)bc * 256 + 2 * y) * 256 + 2 * x;
    float sc = aff[2 * bc], bi = aff[2 * bc + 1];
    float s = p[0] + p[1] + p[256] + p[257];
    out[idx] = fmaf(s * 0.25f, sc, bi);
}

// ---------------- 1x1 conv (64->4), BN6 affine fused on input ----------------
__global__ __launch_bounds__(256) void conv1x1_kernel(const float* __restrict__ in,
                                                      const float* __restrict__ aff,
                                                      const float* __restrict__ wts,
                                                      float* __restrict__ out) {
    int b = blockIdx.y;
    int p = blockIdx.x * 256 + threadIdx.x;  // pixel 0..16383
    __shared__ float wsh[4][64];
    __shared__ float sc[64], bi[64];
    int tid = threadIdx.x;
    wsh[tid >> 6][tid & 63] = wts[b * 256 + tid];
    if (tid < 64) {
        sc[tid] = aff[(b * 64 + tid) * 2];
        bi[tid] = aff[(b * 64 + tid) * 2 + 1];
    }
    __syncthreads();
    float acc[4] = {0.f, 0.f, 0.f, 0.f};
    const float* pin = in + (size_t)b * 64 * 16384 + p;
#pragma unroll 8
    for (int ci = 0; ci < 64; ci++) {
        float v = fmaf(pin[(size_t)ci * 16384], sc[ci], bi[ci]);
#pragma unroll
        for (int co = 0; co < 4; co++) acc[co] = fmaf(v, wsh[co][ci], acc[co]);
    }
#pragma unroll
    for (int co = 0; co < 4; co++) out[((size_t)b * 4 + co) * 16384 + p] = acc[co];
}

// ---------------- bilinear x2 (align_corners) + residual add ----------------
__global__ void up_add_kernel(const float* __restrict__ in, const float* __restrict__ x,
                              float* __restrict__ out) {
    int idx = blockIdx.x * 256 + threadIdx.x;
    if (idx >= 16 * 4 * 256 * 256) return;
    int ox = idx & 255;
    int oy = (idx >> 8) & 255;
    int bc = idx >> 16;  // b*4 + c
    const float r = (float)(127.0 / 255.0);
    float px = ox * r, py = oy * r;
    int x0 = (int)px, y0 = (int)py;
    float fx = px - x0, fy = py - y0;
    int x1 = min(x0 + 1, 127), y1 = min(y0 + 1, 127);
    const float* p = in + (size_t)bc * 16384;
    float v00 = p[y0 * 128 + x0], v01 = p[y0 * 128 + x1];
    float v10 = p[y1 * 128 + x0], v11 = p[y1 * 128 + x1];
    float v0 = v00 * (1.f - fx) + v01 * fx;
    float v1 = v10 * (1.f - fx) + v11 * fx;
    out[idx] = v0 * (1.f - fy) + v1 * fy + x[idx];
}

// ---------------- host-side smem size mirror ----------------
static int smem_bytes(int COUT_B, int DIL, int TH) {
    int R = 2 * DIL;
    int PX = 32 + 2 * R, PY = TH + 2 * R;
    int PLANE0 = PX * PY;
    int PS = PLANE0 + ((4 - PLANE0 % 16) + 16) % 16;
    return (25 * 8 * (COUT_B + 4) + 8 * PS) * 8;
}

// ---------------- launch ----------------
extern "C" void kernel_launch(void* const* d_in, const int* in_sizes, int n_in,
                              void* d_out, int out_size) {
    const float* x = (const float*)d_in[0];
    const int* action = (const int*)d_in[1];
    const float* w[7];
    const float* wb[7];
    for (int i = 0; i < 7; i++) {
        w[i] = (const float*)d_in[2 + 2 * i];
        wb[i] = (const float*)d_in[3 + 2 * i];
    }
    const float* bns[7];
    const float* bnb[7];
    for (int i = 0; i < 7; i++) {
        bns[i] = (const float*)d_in[16 + 2 * i];
        bnb[i] = (const float*)d_in[17 + 2 * i];
    }

    uint2 *k1, *k2, *k3, *k4, *k5, *k6;
    float* k7;
    float *t1, *t2, *t3, *t4, *t5, *t6, *t7, *t8, *aff;
    cudaGetSymbolAddress((void**)&k1, g_k1);
    cudaGetSymbolAddress((void**)&k2, g_k2);
    cudaGetSymbolAddress((void**)&k3, g_k3);
    cudaGetSymbolAddress((void**)&k4, g_k4);
    cudaGetSymbolAddress((void**)&k5, g_k5);
    cudaGetSymbolAddress((void**)&k6, g_k6);
    cudaGetSymbolAddress((void**)&k7, g_k7);
    cudaGetSymbolAddress((void**)&t1, g_t1);
    cudaGetSymbolAddress((void**)&t2, g_t2);
    cudaGetSymbolAddress((void**)&t3, g_t3);
    cudaGetSymbolAddress((void**)&t4, g_t4);
    cudaGetSymbolAddress((void**)&t5, g_t5);
    cudaGetSymbolAddress((void**)&t6, g_t6);
    cudaGetSymbolAddress((void**)&t7, g_t7);
    cudaGetSymbolAddress((void**)&t8, g_t8);
    cudaGetSymbolAddress((void**)&aff, g_aff);

    const int AOFF = 16 * 64 * 2;

    // opt-in dynamic smem (idempotent)
    cudaFuncSetAttribute(conv5_bf16_kernel<4, 16, 16, 256, 2, 8, true, false>,
                         cudaFuncAttributeMaxDynamicSharedMemorySize, smem_bytes(16, 2, 8));
    cudaFuncSetAttribute(conv5_bf16_kernel<16, 16, 16, 256, 1, 16, true, true>,
                         cudaFuncAttributeMaxDynamicSharedMemorySize, smem_bytes(16, 1, 16));
    cudaFuncSetAttribute(conv5_bf16_kernel<16, 32, 32, 128, 2, 8, false, false>,
                         cudaFuncAttributeMaxDynamicSharedMemorySize, smem_bytes(32, 2, 8));
    cudaFuncSetAttribute(conv5_bf16_kernel<32, 32, 32, 128, 1, 16, true, true>,
                         cudaFuncAttributeMaxDynamicSharedMemorySize, smem_bytes(32, 1, 16));
    cudaFuncSetAttribute(conv5_bf16_kernel<32, 64, 32, 128, 2, 8, true, false>,
                         cudaFuncAttributeMaxDynamicSharedMemorySize, smem_bytes(32, 2, 8));
    cudaFuncSetAttribute(conv5_bf16_kernel<64, 64, 32, 128, 1, 16, true, true>,
                         cudaFuncAttributeMaxDynamicSharedMemorySize, smem_bytes(32, 1, 16));

    // generate per-batch conv kernels (bf16 hi/lo split, mma layout)
    {
        int t;
        t = 16 * 1 * 25 * 8 * 16;
        genw_bf16_kernel<<<(t + 255) / 256, 256>>>(w[0], wb[0], action, k1, 4, 1, 16);
        genw_bf16_kernel<<<(t + 255) / 256, 256>>>(w[1], wb[1], action, k2, 16, 1, 16);
        t = 16 * 1 * 25 * 8 * 32;
        genw_bf16_kernel<<<(t + 255) / 256, 256>>>(w[2], wb[2], action, k3, 16, 1, 32);
        t = 16 * 2 * 25 * 8 * 32;
        genw_bf16_kernel<<<(t + 255) / 256, 256>>>(w[3], wb[3], action, k4, 32, 2, 32);
        t = 16 * 2 * 25 * 8 * 64;
        genw_bf16_kernel<<<(t + 255) / 256, 256>>>(w[4], wb[4], action, k5, 32, 2, 64);
        t = 16 * 4 * 25 * 8 * 64;
        genw_bf16_kernel<<<(t + 255) / 256, 256>>>(w[5], wb[5], action, k6, 64, 4, 64);
    }
    genw_kernel<<<(256 * 16 + 255) / 256, 256>>>(w[6], wb[6], action, k7, 256);

    // bn0 stats on x
    stats_kernel<65536><<<16 * 4, 256>>>(x, bns[0], bnb[0], aff + 0 * AOFF, 4);
    // conv1: bn0(x) -> t1
    conv5_bf16_kernel<4, 16, 16, 256, 2, 8, true, false>
        <<<dim3(8, 32, 16), 256, smem_bytes(16, 2, 8)>>>(x, aff + 0 * AOFF, k1, t1);
    // bn1 stats
    stats_kernel<65536><<<16 * 16, 256>>>(t1, bns[1], bnb[1], aff + 1 * AOFF, 16);
    // conv2: relu(bn1(t1)) -> t2
    conv5_bf16_kernel<16, 16, 16, 256, 1, 16, true, true>
        <<<dim3(8, 16, 16), 256, smem_bytes(16, 1, 16)>>>(t1, aff + 1 * AOFF, k2, t2);
    // bn2 stats
    stats_kernel<65536><<<16 * 16, 256>>>(t2, bns[2], bnb[2], aff + 2 * AOFF, 16);
    // avgpool(bn2(t2)) -> t3 (normalized)
    avgpool_kernel<<<(16 * 16 * 128 * 128 + 255) / 256, 256>>>(t2, aff + 2 * AOFF, t3);
    // conv3: t3 -> t4
    conv5_bf16_kernel<16, 32, 32, 128, 2, 8, false, false>
        <<<dim3(4, 16, 16), 256, smem_bytes(32, 2, 8)>>>(t3, aff, k3, t4);
    // bn3 stats
    stats_kernel<16384><<<16 * 32, 256>>>(t4, bns[3], bnb[3], aff + 3 * AOFF, 32);
    // conv4: relu(bn3(t4)) -> t5
    conv5_bf16_kernel<32, 32, 32, 128, 1, 16, true, true>
        <<<dim3(4, 8, 16), 256, smem_bytes(32, 1, 16)>>>(t4, aff + 3 * AOFF, k4, t5);
    // bn4 stats
    stats_kernel<16384><<<16 * 32, 256>>>(t5, bns[4], bnb[4], aff + 4 * AOFF, 32);
    // conv5: bn4(t5) -> t6
    conv5_bf16_kernel<32, 64, 32, 128, 2, 8, true, false>
        <<<dim3(4, 32, 16), 256, smem_bytes(32, 2, 8)>>>(t5, aff + 4 * AOFF, k5, t6);
    // bn5 stats
    stats_kernel<16384><<<16 * 64, 256>>>(t6, bns[5], bnb[5], aff + 5 * AOFF, 64);
    // conv6: relu(bn5(t6)) -> t7
    conv5_bf16_kernel<64, 64, 32, 128, 1, 16, true, true>
        <<<dim3(4, 16, 16), 256, smem_bytes(32, 1, 16)>>>(t6, aff + 5 * AOFF, k6, t7);
    // bn6 stats
    stats_kernel<16384><<<16 * 64, 256>>>(t7, bns[6], bnb[6], aff + 6 * AOFF, 64);
    // conv7 1x1: bn6(t7) -> t8
    conv1x1_kernel<<<dim3(64, 16), 256>>>(t7, aff + 6 * AOFF, k7, t8);
    // upsample + residual
    up_add_kernel<<<(16 * 4 * 256 * 256 + 255) / 256, 256>>>(t8, x, (float*)d_out);
}